// round 13
// baseline (speedup 1.0000x reference)
#include <cuda_runtime.h>
#include <cstdint>

#define NN 3072
#define DD 128
#define HID 256
#define NAA 20
#define NH 8
#define TM 16          // rows per prep block
#define JT 64          // j-tile per pair CTA
#define IT 16          // i-rows per pair CTA
#define TI 4           // i-rows per pair thread

typedef unsigned long long ull;

// Scratch (allocation-free rule: __device__ globals)
// dgate, block-transposed: float index = jb*10240 + (xp*4 + b/2)*256 + jj*4 + (b&1)*2 + (x&1)
__device__ __align__(16) float g_dgT[48 * 40 * 256];
// ctilde: row layout [xp*16 + b*2 + e], 160 floats per row
__device__ __align__(16) float g_ctilde[NN * 160];

__device__ __forceinline__ float gelu_tanh(float v) {
    float u = 0.7978845608028654f * (v + 0.044715f * v * v * v);
    float e = __expf(-2.0f * u);
    return v / (1.0f + e);
}

__device__ __forceinline__ ull fma2(ull a, ull b, ull c) {
    ull d;
    asm("fma.rn.f32x2 %0, %1, %2, %3;" : "=l"(d) : "l"(a), "l"(b), "l"(c));
    return d;
}

__device__ __forceinline__ uint32_t smem_u32(const void* p) {
    uint32_t a;
    asm("{ .reg .u64 t; cvta.to.shared.u64 t, %1; cvt.u32.u64 %0, t; }" : "=r"(a) : "l"(p));
    return a;
}

__device__ __forceinline__ void cp16(uint32_t dst, const void* src) {
    asm volatile("cp.async.cg.shared.global [%0], [%1], 16;" :: "r"(dst), "l"(src) : "memory");
}
#define CP_COMMIT()  asm volatile("cp.async.commit_group;" ::: "memory")
#define CP_WAIT(n)   asm volatile("cp.async.wait_group %0;" :: "n"(n) : "memory")

// ---- prep smem overlay map (static, ~58.5 KB) ----
#define OFF_XS   0          // [16][128] f       8192
#define OFF_HS   8192       // [16][256] f      16384
#define OFF_FS   24576      // [16][128] f       8192
#define OFF_DCS  32768      // [16][160] f      10240
#define OFF_DGS  43008      // [40*64]   f      10240
#define OFF_IWS  53248      // 1280      f       5120
#define OFF_AAS  58368      // 16        i         64
#define OFF_W1B  24576      // 2 x 8192  (over FS+DCS; free in stage1)
#define OFF_W2B  32768      // 2 x 4096  (over DCS; free in stage2)
#define OFF_W3B  0          // 2 x 10240 (over XS+HS; free in stage3)
#define PREP_SMEM 58432

// ============================================================================
// Kernel A: prep with cp.async double-buffered weight staging
// ============================================================================
__global__ __launch_bounds__(256) void prep_kernel(
    const float* __restrict__ local, const int* __restrict__ aa,
    const float* __restrict__ W1, const float* __restrict__ W2,
    const float* __restrict__ Wc, const float* __restrict__ Wg,
    const float* __restrict__ iw)
{
    __shared__ __align__(16) char smbuf[PREP_SMEM];
    float (*xs)[DD]   = (float (*)[DD])(smbuf + OFF_XS);
    float (*Hs)[HID]  = (float (*)[HID])(smbuf + OFF_HS);
    float (*Fs)[DD]   = (float (*)[DD])(smbuf + OFF_FS);
    float (*dcs)[160] = (float (*)[160])(smbuf + OFF_DCS);
    float *dgs        = (float*)(smbuf + OFF_DGS);
    float *iws        = (float*)(smbuf + OFF_IWS);
    int   *aas        = (int*)(smbuf + OFF_AAS);

    const uint32_t sbp = smem_u32(smbuf);
    const int tid = threadIdx.x;
    const int r0 = blockIdx.x * TM;

    // ---- stage 1 chunk-0 prefetch first (independent of xs/iws loads) ----
    {
        uint32_t d = sbp + OFF_W1B + tid * 16;
        const char* s = (const char*)W1 + tid * 16;
        cp16(d, s); cp16(d + 4096, s + 4096);
        CP_COMMIT();
    }

    for (int t = tid; t < TM * DD; t += 256) {
        int r = t / DD, k = t % DD;
        xs[r][k] = local[(size_t)(r0 + r) * DD + k];
    }
    for (int t = tid; t < NH * NH * NAA; t += 256) iws[t] = iw[t];
    if (tid < TM) aas[tid] = aa[r0 + tid];

    // ---- stage 1: H = gelu(local @ W1[:128] + W1[128+aa]); 16 chunks of 8k ----
    {
        float acc[TM];
#pragma unroll
        for (int r = 0; r < TM; r++) acc[r] = 0.f;
        const int col = tid;

        for (int ch = 0; ch < 16; ch++) {
            if (ch < 15) {
                uint32_t d = sbp + OFF_W1B + ((ch + 1) & 1) * 8192 + tid * 16;
                const char* s = (const char*)W1 + (ch + 1) * 8192 + tid * 16;
                cp16(d, s); cp16(d + 4096, s + 4096);
                CP_COMMIT();
                CP_WAIT(1);
            } else {
                CP_WAIT(0);
            }
            __syncthreads();
            const float* wb = (const float*)(smbuf + OFF_W1B + (ch & 1) * 8192);
            const int k0 = ch * 8;
#pragma unroll
            for (int kk = 0; kk < 8; kk += 4) {
                float w0 = wb[(kk + 0) * HID + col];
                float w1 = wb[(kk + 1) * HID + col];
                float w2 = wb[(kk + 2) * HID + col];
                float w3 = wb[(kk + 3) * HID + col];
#pragma unroll
                for (int r = 0; r < TM; r++) {
                    float4 xv = *(const float4*)&xs[r][k0 + kk];
                    acc[r] = fmaf(xv.x, w0, fmaf(xv.y, w1, fmaf(xv.z, w2, fmaf(xv.w, w3, acc[r]))));
                }
            }
            __syncthreads();
        }

        // stage-2 chunk-0 prefetch overlaps the gelu tail (regions disjoint)
        {
            uint32_t d = sbp + OFF_W2B + tid * 16;
            cp16(d, (const char*)W2 + tid * 16);
            CP_COMMIT();
        }
#pragma unroll
        for (int r = 0; r < TM; r++) {
            acc[r] += W1[(size_t)(DD + aas[r]) * HID + col];
            Hs[r][col] = gelu_tanh(acc[r]);
        }
    }
    __syncthreads();

    // ---- stage 2: F = H @ W2; 32 chunks of 8k (buf 4 KB x2) ----
    {
        float acc[8];
#pragma unroll
        for (int r = 0; r < 8; r++) acc[r] = 0.f;
        const int col = tid & 127;
        const int rb = (tid >> 7) * 8;

        for (int ch = 0; ch < 32; ch++) {
            if (ch < 31) {
                uint32_t d = sbp + OFF_W2B + ((ch + 1) & 1) * 4096 + tid * 16;
                cp16(d, (const char*)W2 + (ch + 1) * 4096 + tid * 16);
                CP_COMMIT();
                CP_WAIT(1);
            } else {
                CP_WAIT(0);
            }
            __syncthreads();
            const float* wb = (const float*)(smbuf + OFF_W2B + (ch & 1) * 4096);
            const int k0 = ch * 8;
#pragma unroll
            for (int kk = 0; kk < 8; kk += 4) {
                float w0 = wb[(kk + 0) * DD + col];
                float w1 = wb[(kk + 1) * DD + col];
                float w2 = wb[(kk + 2) * DD + col];
                float w3 = wb[(kk + 3) * DD + col];
#pragma unroll
                for (int r = 0; r < 8; r++) {
                    float4 hv = *(const float4*)&Hs[rb + r][k0 + kk];
                    acc[r] = fmaf(hv.x, w0, fmaf(hv.y, w1, fmaf(hv.z, w2, fmaf(hv.w, w3, acc[r]))));
                }
            }
            __syncthreads();
        }

        // stage-3 chunk-0 prefetch (buf over dead xs/Hs) before Fs stores
        for (int t = tid; t < 640; t += 256) {
            int idx = t * 4;              // float index in [8][320]
            int k = idx / 320, cp = idx % 320;
            const float* src = (cp < 160) ? (Wc + (size_t)k * 160 + cp)
                                          : (Wg + (size_t)k * 160 + (cp - 160));
            cp16(sbp + OFF_W3B + t * 16, src);
        }
        CP_COMMIT();

#pragma unroll
        for (int r = 0; r < 8; r++) Fs[rb + r][col] = acc[r];
    }
    __syncthreads();

    // ---- stage 3: 640 balanced (col, row-half) jobs; weights from smem ----
    {
        float acc3[3][8];
#pragma unroll
        for (int j = 0; j < 3; j++)
#pragma unroll
            for (int r = 0; r < 8; r++) acc3[j][r] = 0.f;
        const int nj = (tid < 128) ? 3 : 2;       // jobs: tid, tid+256, tid+512

        for (int ch = 0; ch < 16; ch++) {
            if (ch < 15) {
                const int kb = (ch + 1) * 8;
                for (int t = tid; t < 640; t += 256) {
                    int idx = t * 4;
                    int k = idx / 320, cp = idx % 320;
                    const float* src = (cp < 160) ? (Wc + (size_t)(kb + k) * 160 + cp)
                                                  : (Wg + (size_t)(kb + k) * 160 + (cp - 160));
                    cp16(sbp + OFF_W3B + ((ch + 1) & 1) * 10240 + t * 16, src);
                }
                CP_COMMIT();
                CP_WAIT(1);
            } else {
                CP_WAIT(0);
            }
            __syncthreads();
            const float* wb = (const float*)(smbuf + OFF_W3B + (ch & 1) * 10240);
            const int k0 = ch * 8;
            for (int j = 0; j < nj; j++) {
                const int c0 = tid + j * 256;
                const int c  = c0 >> 1;
                const int rb = (c0 & 1) * 8;
#pragma unroll
                for (int kk = 0; kk < 8; kk += 4) {
                    float w0 = wb[(kk + 0) * 320 + c];
                    float w1 = wb[(kk + 1) * 320 + c];
                    float w2 = wb[(kk + 2) * 320 + c];
                    float w3 = wb[(kk + 3) * 320 + c];
#pragma unroll
                    for (int r = 0; r < 8; r++) {
                        float4 fv = *(const float4*)&Fs[rb + r][k0 + kk];
                        acc3[j][r] = fmaf(fv.x, w0, fmaf(fv.y, w1,
                                     fmaf(fv.z, w2, fmaf(fv.w, w3, acc3[j][r]))));
                    }
                }
            }
            __syncthreads();
        }

        for (int j = 0; j < nj; j++) {
            const int c0 = tid + j * 256;
            const int c  = c0 >> 1;
            const int rb = (c0 & 1) * 8;
            if (c < 160) {
#pragma unroll
                for (int r = 0; r < 8; r++) dcs[rb + r][c] = acc3[j][r];
            } else {
                int cc = c - 160;
                int b = cc / NAA, x = cc % NAA;
                int row = (x >> 1) * 4 + (b >> 1);
                int e   = (b & 1) * 2 + (x & 1);
#pragma unroll
                for (int r = 0; r < 8; r++)
                    dgs[row * 64 + (rb + r) * 4 + e] = gelu_tanh(acc3[j][r]);
            }
        }
    }
    __syncthreads();

    // ---- coalesced copy: dgs -> g_dgT ----
    {
        const int jb = r0 >> 6;
        const int jo = (r0 & 63) >> 2;
        const float4* src = (const float4*)dgs;
        float4* dst = (float4*)g_dgT;
        for (int t = tid; t < 640; t += 256) {
            int row = t >> 4, q = t & 15;
            dst[(size_t)jb * 2560 + row * 64 + jo * 4 + q] = src[row * 16 + q];
        }
    }

    // ---- stage 4: ctilde ----
    for (int t = tid; t < TM * 160; t += 256) {
        int r = t / 160, rem = t % 160;
        int b = rem / NAA, x = rem % NAA;
        float s = 0.f;
#pragma unroll
        for (int a = 0; a < NH; a++)
            s = fmaf(dcs[r][a * NAA + x], iws[a * 160 + b * NAA + x], s);
        g_ctilde[(size_t)(r0 + r) * 160 + (x >> 1) * 16 + b * 2 + (x & 1)] = s;
    }

    // ---- PDL: make writes visible, then allow dependent (pair) grid ----
    __threadfence();
    asm volatile("griddepcontrol.launch_dependents;" ::: "memory");
}

// ============================================================================
// Kernel B: pairwise bilinear + log_softmax (exact R8 body + PDL wait)
// ============================================================================
#define SM_GS   0
#define SM_CS   40960
#define SM_STG  51200
#define SM_MBAR 92160
#define SM_TOT  92176

__global__ __launch_bounds__(256, 2) void pair_kernel(float* __restrict__ out)
{
    extern __shared__ __align__(16) char sm[];

    asm volatile("griddepcontrol.wait;" ::: "memory");

    const ulonglong2* gs2 = (const ulonglong2*)(sm + SM_GS);  // [40][64]
    const float*      cs  = (const float*)(sm + SM_CS);       // [16][160]

    const uint32_t sb   = smem_u32(sm);
    const uint32_t mbar = sb + SM_MBAR;

    const int tid  = threadIdx.x;
    const int lane = tid & 31;
    const int wid  = tid >> 5;
    const int i0   = blockIdx.x * IT;
    const int jb   = blockIdx.y;

    if (tid == 0) {
        asm volatile("mbarrier.init.shared::cta.b64 [%0], %1;" :: "r"(mbar), "r"(1) : "memory");
    }
    __syncthreads();
    if (tid == 0) {
        asm volatile("mbarrier.arrive.expect_tx.shared::cta.b64 _, [%0], %1;"
                     :: "r"(mbar), "r"(51200) : "memory");
        asm volatile("cp.async.bulk.shared::cta.global.mbarrier::complete_tx::bytes [%0], [%1], %2, [%3];"
                     :: "r"(sb + SM_GS), "l"(g_dgT + (size_t)jb * 10240), "r"(40960), "r"(mbar) : "memory");
        asm volatile("cp.async.bulk.shared::cta.global.mbarrier::complete_tx::bytes [%0], [%1], %2, [%3];"
                     :: "r"(sb + SM_CS), "l"(g_ctilde + (size_t)i0 * 160), "r"(10240), "r"(mbar) : "memory");
    }
    asm volatile("{\n\t.reg .pred P;\n"
                 "W%=: mbarrier.try_wait.parity.shared::cta.b64 P, [%0], 0;\n\t"
                 "@!P bra W%=;\n\t}" :: "r"(mbar) : "memory");
    __syncthreads();

    const int jj = tid & 63;
    const int ig = tid >> 6;

    ull acc[TI][10];
#pragma unroll
    for (int r = 0; r < TI; r++)
#pragma unroll
        for (int q = 0; q < 10; q++) acc[r][q] = 0ULL;

#pragma unroll
    for (int xp = 0; xp < 10; xp++) {
        ulonglong2 g0  = gs2[(xp * 4 + 0) * 64 + jj];
        ulonglong2 g1  = gs2[(xp * 4 + 1) * 64 + jj];
        ulonglong2 g2v = gs2[(xp * 4 + 2) * 64 + jj];
        ulonglong2 g3  = gs2[(xp * 4 + 3) * 64 + jj];
#pragma unroll
        for (int r = 0; r < TI; r++) {
            const float* cp = cs + (ig * 4 + r) * 160 + xp * 16;
            longlong2 ca = *(const longlong2*)(cp);
            longlong2 cb = *(const longlong2*)(cp + 4);
            longlong2 cc = *(const longlong2*)(cp + 8);
            longlong2 cd = *(const longlong2*)(cp + 12);
            ull a0 = acc[r][xp];
            a0 = fma2((ull)ca.x, g0.x, a0);
            a0 = fma2((ull)ca.y, g0.y, a0);
            a0 = fma2((ull)cb.x, g1.x, a0);
            a0 = fma2((ull)cb.y, g1.y, a0);
            a0 = fma2((ull)cc.x, g2v.x, a0);
            a0 = fma2((ull)cc.y, g2v.y, a0);
            a0 = fma2((ull)cd.x, g3.x, a0);
            a0 = fma2((ull)cd.y, g3.y, a0);
            acc[r][xp] = a0;
        }
    }

    // ---- epilogue: log_softmax, stage (conflict-free STS.128), bulk store ----
    float* wbuf = (float*)(sm + SM_STG) + wid * 1280;
    const uint32_t wbuf_u32 = sb + SM_STG + wid * 5120;
    const int col0 = jb * JT + (wid & 1) * 32;

#pragma unroll
    for (int r = 0; r < TI; r++) {
        float* st = wbuf + (r & 1) * 640;
        if (r >= 2 && lane == 0)
            asm volatile("cp.async.bulk.wait_group.read 1;" ::: "memory");
        __syncwarp();

        float l[20];
#pragma unroll
        for (int q = 0; q < 10; q++) {
            l[2 * q]     = __uint_as_float((unsigned)(acc[r][q] & 0xffffffffu));
            l[2 * q + 1] = __uint_as_float((unsigned)(acc[r][q] >> 32));
        }
        float m = l[0];
#pragma unroll
        for (int x = 1; x < 20; x++) m = fmaxf(m, l[x]);
        float s = 0.f;
#pragma unroll
        for (int x = 0; x < 20; x++) s += __expf(l[x] - m);
        float lse = m + __logf(s);

        float* tp = st + lane * 20;
#pragma unroll
        for (int q = 0; q < 5; q++) {
            float4 o = make_float4(l[4 * q] - lse, l[4 * q + 1] - lse,
                                   l[4 * q + 2] - lse, l[4 * q + 3] - lse);
            *(float4*)(tp + 4 * q) = o;
        }
        __syncwarp();

        if (lane == 0) {
            float* gdst = out + ((size_t)(i0 + ig * 4 + r) * NN + col0) * NAA;
            asm volatile("fence.proxy.async.shared::cta;" ::: "memory");
            asm volatile("cp.async.bulk.global.shared::cta.bulk_group [%0], [%1], %2;"
                         :: "l"(gdst), "r"(wbuf_u32 + (r & 1) * 2560), "r"(2560) : "memory");
            asm volatile("cp.async.bulk.commit_group;" ::: "memory");
        }
    }
    if (lane == 0)
        asm volatile("cp.async.bulk.wait_group 0;" ::: "memory");
}

// ============================================================================
extern "C" void kernel_launch(void* const* d_in, const int* in_sizes, int n_in,
                              void* d_out, int out_size)
{
    const float* local = (const float*)d_in[0];
    const int*   aa    = (const int*)d_in[1];
    const float* W1    = (const float*)d_in[2];
    const float* W2    = (const float*)d_in[3];
    const float* Wc    = (const float*)d_in[4];
    const float* Wg    = (const float*)d_in[5];
    const float* iw    = (const float*)d_in[6];
    float* out = (float*)d_out;

    prep_kernel<<<NN / TM, 256>>>(local, aa, W1, W2, Wc, Wg, iw);

    cudaFuncSetAttribute(pair_kernel, cudaFuncAttributeMaxDynamicSharedMemorySize, SM_TOT);

    cudaLaunchConfig_t cfg = {};
    cfg.gridDim = dim3(NN / IT, NN / JT);
    cfg.blockDim = dim3(256, 1, 1);
    cfg.dynamicSmemBytes = SM_TOT;
    cfg.stream = 0;
    cudaLaunchAttribute attrs[1];
    attrs[0].id = cudaLaunchAttributeProgrammaticStreamSerialization;
    attrs[0].val.programmaticStreamSerializationAllowed = 1;
    cfg.attrs = attrs;
    cfg.numAttrs = 1;
    cudaLaunchKernelEx(&cfg, pair_kernel, out);
}

// round 14
// speedup vs baseline: 1.0854x; 1.0854x over previous
#include <cuda_runtime.h>
#include <cstdint>

#define NN 3072
#define DD 128
#define HID 256
#define NAA 20
#define NH 8
#define TM 16          // rows per prep block
#define JT 64          // j-tile per pair CTA
#define IT 16          // i-rows per pair CTA
#define TI 4           // i-rows per pair thread

typedef unsigned long long ull;

// Scratch (allocation-free rule: __device__ globals)
// dgate, block-transposed: float index = jb*10240 + (xp*4 + b/2)*256 + jj*4 + (b&1)*2 + (x&1)
__device__ __align__(16) float g_dgT[48 * 40 * 256];
// ctilde: row layout [xp*16 + b*2 + e], 160 floats per row
__device__ __align__(16) float g_ctilde[NN * 160];

__device__ __forceinline__ float gelu_tanh(float v) {
    float u = 0.7978845608028654f * (v + 0.044715f * v * v * v);
    float e = __expf(-2.0f * u);
    return v / (1.0f + e);
}

__device__ __forceinline__ ull fma2(ull a, ull b, ull c) {
    ull d;
    asm("fma.rn.f32x2 %0, %1, %2, %3;" : "=l"(d) : "l"(a), "l"(b), "l"(c));
    return d;
}

__device__ __forceinline__ uint32_t smem_u32(const void* p) {
    uint32_t a;
    asm("{ .reg .u64 t; cvta.to.shared.u64 t, %1; cvt.u32.u64 %0, t; }" : "=r"(a) : "l"(p));
    return a;
}

__device__ __forceinline__ void cp16(uint32_t dst, const void* src) {
    asm volatile("cp.async.cg.shared.global [%0], [%1], 16;" :: "r"(dst), "l"(src) : "memory");
}
#define CP_COMMIT()  asm volatile("cp.async.commit_group;" ::: "memory")
#define CP_WAIT(n)   asm volatile("cp.async.wait_group %0;" :: "n"(n) : "memory")

// Stage one 1KB chunk (8 k-rows x 32 cols f32) into a warp-private buffer.
// Warp-collective: each lane copies two 16B segments. No CTA sync needed.
__device__ __forceinline__ void stage_chunk(uint32_t dst, const char* srcbase, int rowStride) {
    const int lane = threadIdx.x & 31;
    const int s0 = lane, s1 = lane + 32;
    cp16(dst + s0 * 16, srcbase + (s0 >> 3) * rowStride + (s0 & 7) * 16);
    cp16(dst + s1 * 16, srcbase + (s1 >> 3) * rowStride + (s1 & 7) * 16);
    CP_COMMIT();
}

// ---- prep smem overlay map (static, ~58.5 KB) ----
#define OFF_XS   0          // [16][128] f       8192
#define OFF_HS   8192       // [16][256] f      16384
#define OFF_FS   24576      // [16][128] f       8192
#define OFF_DCS  32768      // [16][160] f      10240
#define OFF_DGS  43008      // [40*64]   f      10240
#define OFF_IWS  53248      // 1280      f       5120
#define OFF_AAS  58368      // 16        i         64
// warp-private weight double-buffers (8 warps x 2 x 1KB = 16KB), per-stage overlay:
#define OFF_S1B  24576      // over FS+DCS (dead in stage 1)
#define OFF_S2B  32768      // over DCS+DGS[0:6K] (dead in stage 2)
#define OFF_S3B  0          // over XS+HS[0:8K]  (dead in stage 3)
#define PREP_SMEM 58432

// ============================================================================
// Kernel A: prep with warp-private cp.async weight staging (no extra barriers)
// ============================================================================
__global__ __launch_bounds__(256) void prep_kernel(
    const float* __restrict__ local, const int* __restrict__ aa,
    const float* __restrict__ W1, const float* __restrict__ W2,
    const float* __restrict__ Wc, const float* __restrict__ Wg,
    const float* __restrict__ iw)
{
    __shared__ __align__(16) char smbuf[PREP_SMEM];
    float (*xs)[DD]   = (float (*)[DD])(smbuf + OFF_XS);
    float (*Hs)[HID]  = (float (*)[HID])(smbuf + OFF_HS);
    float (*Fs)[DD]   = (float (*)[DD])(smbuf + OFF_FS);
    float (*dcs)[160] = (float (*)[160])(smbuf + OFF_DCS);
    float *dgs        = (float*)(smbuf + OFF_DGS);
    float *iws        = (float*)(smbuf + OFF_IWS);
    int   *aas        = (int*)(smbuf + OFF_AAS);

    const uint32_t sbp = smem_u32(smbuf);
    const int tid  = threadIdx.x;
    const int lane = tid & 31;
    const int w    = tid >> 5;
    const int r0   = blockIdx.x * TM;

    for (int t = tid; t < TM * DD; t += 256) {
        int r = t / DD, k = t % DD;
        xs[r][k] = local[(size_t)(r0 + r) * DD + k];
    }
    for (int t = tid; t < NH * NH * NAA; t += 256) iws[t] = iw[t];
    if (tid < TM) aas[tid] = aa[r0 + tid];
    __syncthreads();

    // ---- stage 1: H = gelu(local @ W1[:128] + W1[128+aa]) ----
    // warp w owns cols 32w..32w+31; 16 chunks of 8 k-rows, double-buffered
    {
        const uint32_t b1 = sbp + OFF_S1B + w * 2048;
        const char* w1base = (const char*)W1 + w * 128;   // 32 cols * 4B
        stage_chunk(b1, w1base, 1024);

        float acc[TM];
#pragma unroll
        for (int r = 0; r < TM; r++) acc[r] = 0.f;
        const int col = w * 32 + lane;

        for (int ch = 0; ch < 16; ch++) {
            if (ch < 15) {
                stage_chunk(b1 + ((ch + 1) & 1) * 1024, w1base + (ch + 1) * 8192, 1024);
                CP_WAIT(1);
            } else {
                CP_WAIT(0);
            }
            const float* wb = (const float*)(smbuf + OFF_S1B + w * 2048 + (ch & 1) * 1024);
            const int k0 = ch * 8;
#pragma unroll
            for (int kk = 0; kk < 8; kk += 4) {
                float w0 = wb[(kk + 0) * 32 + lane];
                float w1v = wb[(kk + 1) * 32 + lane];
                float w2 = wb[(kk + 2) * 32 + lane];
                float w3 = wb[(kk + 3) * 32 + lane];
#pragma unroll
                for (int r = 0; r < TM; r++) {
                    float4 xv = *(const float4*)&xs[r][k0 + kk];
                    acc[r] = fmaf(xv.x, w0, fmaf(xv.y, w1v, fmaf(xv.z, w2, fmaf(xv.w, w3, acc[r]))));
                }
            }
        }
#pragma unroll
        for (int r = 0; r < TM; r++) {
            acc[r] += W1[(size_t)(DD + aas[r]) * HID + col];
            Hs[r][col] = gelu_tanh(acc[r]);
        }
    }
    __syncthreads();

    // ---- stage 2: F = H @ W2 ----
    // warp w: rows (w>>2)*8..+7, cols (w&3)*32+lane; 32 chunks of 8 k-rows
    {
        const uint32_t b2 = sbp + OFF_S2B + w * 2048;
        const char* w2base = (const char*)W2 + (w & 3) * 128;
        stage_chunk(b2, w2base, 512);

        float acc[8];
#pragma unroll
        for (int r = 0; r < 8; r++) acc[r] = 0.f;
        const int col = (w & 3) * 32 + lane;
        const int rb = (w >> 2) * 8;

        for (int ch = 0; ch < 32; ch++) {
            if (ch < 31) {
                stage_chunk(b2 + ((ch + 1) & 1) * 1024, w2base + (ch + 1) * 4096, 512);
                CP_WAIT(1);
            } else {
                CP_WAIT(0);
            }
            const float* wb = (const float*)(smbuf + OFF_S2B + w * 2048 + (ch & 1) * 1024);
            const int k0 = ch * 8;
#pragma unroll
            for (int kk = 0; kk < 8; kk += 4) {
                float w0 = wb[(kk + 0) * 32 + lane];
                float w1v = wb[(kk + 1) * 32 + lane];
                float w2 = wb[(kk + 2) * 32 + lane];
                float w3 = wb[(kk + 3) * 32 + lane];
#pragma unroll
                for (int r = 0; r < 8; r++) {
                    float4 hv = *(const float4*)&Hs[rb + r][k0 + kk];
                    acc[r] = fmaf(hv.x, w0, fmaf(hv.y, w1v, fmaf(hv.z, w2, fmaf(hv.w, w3, acc[r]))));
                }
            }
        }
#pragma unroll
        for (int r = 0; r < 8; r++) Fs[rb + r][col] = acc[r];
    }
    __syncthreads();

    // ---- stage 3: dcode = F@Wc (smem), dgate = gelu(F@Wg) -> dgs ----
    // pass A: c = 32w+lane (0..255); pass B (warps 0,1): c = 256+32w+lane
    {
        const uint32_t b3 = sbp + OFF_S3B + w * 2048;

        // pass A
        {
            const int c = w * 32 + lane;
            const float* WpA = (w < 5) ? (Wc + w * 32) : (Wg + (w * 32 - 160));
            stage_chunk(b3, (const char*)WpA, 640);

            float acc[TM];
#pragma unroll
            for (int r = 0; r < TM; r++) acc[r] = 0.f;

            for (int ch = 0; ch < 16; ch++) {
                if (ch < 15) {
                    stage_chunk(b3 + ((ch + 1) & 1) * 1024, (const char*)WpA + (ch + 1) * 5120, 640);
                    CP_WAIT(1);
                } else {
                    CP_WAIT(0);
                }
                const float* wb = (const float*)(smbuf + OFF_S3B + w * 2048 + (ch & 1) * 1024);
                const int k0 = ch * 8;
#pragma unroll
                for (int kk = 0; kk < 8; kk += 4) {
                    float w0 = wb[(kk + 0) * 32 + lane];
                    float w1v = wb[(kk + 1) * 32 + lane];
                    float w2 = wb[(kk + 2) * 32 + lane];
                    float w3 = wb[(kk + 3) * 32 + lane];
#pragma unroll
                    for (int r = 0; r < TM; r++) {
                        float4 fv = *(const float4*)&Fs[r][k0 + kk];
                        acc[r] = fmaf(fv.x, w0, fmaf(fv.y, w1v, fmaf(fv.z, w2, fmaf(fv.w, w3, acc[r]))));
                    }
                }
            }
            if (c < 160) {
#pragma unroll
                for (int r = 0; r < TM; r++) dcs[r][c] = acc[r];
            } else {
                int cc = c - 160;
                int b = cc / NAA, x = cc % NAA;
                int row = (x >> 1) * 4 + (b >> 1);
                int e   = (b & 1) * 2 + (x & 1);
#pragma unroll
                for (int r = 0; r < TM; r++)
                    dgs[row * 64 + r * 4 + e] = gelu_tanh(acc[r]);
            }
        }

        // pass B (warps 0,1 only): c = 256 + 32w + lane -> Wg cols 96+32w+lane
        if (w < 2) {
            const int c = 256 + w * 32 + lane;
            const float* WpB = Wg + 96 + w * 32;
            stage_chunk(b3, (const char*)WpB, 640);

            float acc[TM];
#pragma unroll
            for (int r = 0; r < TM; r++) acc[r] = 0.f;

            for (int ch = 0; ch < 16; ch++) {
                if (ch < 15) {
                    stage_chunk(b3 + ((ch + 1) & 1) * 1024, (const char*)WpB + (ch + 1) * 5120, 640);
                    CP_WAIT(1);
                } else {
                    CP_WAIT(0);
                }
                const float* wb = (const float*)(smbuf + OFF_S3B + w * 2048 + (ch & 1) * 1024);
                const int k0 = ch * 8;
#pragma unroll
                for (int kk = 0; kk < 8; kk += 4) {
                    float w0 = wb[(kk + 0) * 32 + lane];
                    float w1v = wb[(kk + 1) * 32 + lane];
                    float w2 = wb[(kk + 2) * 32 + lane];
                    float w3 = wb[(kk + 3) * 32 + lane];
#pragma unroll
                    for (int r = 0; r < TM; r++) {
                        float4 fv = *(const float4*)&Fs[r][k0 + kk];
                        acc[r] = fmaf(fv.x, w0, fmaf(fv.y, w1v, fmaf(fv.z, w2, fmaf(fv.w, w3, acc[r]))));
                    }
                }
            }
            int cc = c - 160;
            int b = cc / NAA, x = cc % NAA;
            int row = (x >> 1) * 4 + (b >> 1);
            int e   = (b & 1) * 2 + (x & 1);
#pragma unroll
            for (int r = 0; r < TM; r++)
                dgs[row * 64 + r * 4 + e] = gelu_tanh(acc[r]);
        }
    }
    __syncthreads();

    // ---- coalesced copy: dgs -> g_dgT ----
    {
        const int jb = r0 >> 6;
        const int jo = (r0 & 63) >> 2;
        const float4* src = (const float4*)dgs;
        float4* dst = (float4*)g_dgT;
        for (int t = tid; t < 640; t += 256) {
            int row = t >> 4, q = t & 15;
            dst[(size_t)jb * 2560 + row * 64 + jo * 4 + q] = src[row * 16 + q];
        }
    }

    // ---- stage 4: ctilde ----
    for (int t = tid; t < TM * 160; t += 256) {
        int r = t / 160, rem = t % 160;
        int b = rem / NAA, x = rem % NAA;
        float s = 0.f;
#pragma unroll
        for (int a = 0; a < NH; a++)
            s = fmaf(dcs[r][a * NAA + x], iws[a * 160 + b * NAA + x], s);
        g_ctilde[(size_t)(r0 + r) * 160 + (x >> 1) * 16 + b * 2 + (x & 1)] = s;
    }

    // ---- PDL: make writes visible, then allow dependent (pair) grid ----
    __threadfence();
    asm volatile("griddepcontrol.launch_dependents;" ::: "memory");
}

// ============================================================================
// Kernel B: pairwise bilinear + log_softmax (exact R12 — proven ~177 us)
// ============================================================================
#define SM_GS   0
#define SM_CS   40960
#define SM_STG  51200
#define SM_MBAR 92160
#define SM_TOT  92176

__global__ __launch_bounds__(256, 2) void pair_kernel(float* __restrict__ out)
{
    extern __shared__ __align__(16) char sm[];

    asm volatile("griddepcontrol.wait;" ::: "memory");

    const ulonglong2* gs2 = (const ulonglong2*)(sm + SM_GS);  // [40][64]
    const float*      cs  = (const float*)(sm + SM_CS);       // [16][160]

    const uint32_t sb   = smem_u32(sm);
    const uint32_t mbar = sb + SM_MBAR;

    const int tid  = threadIdx.x;
    const int lane = tid & 31;
    const int wid  = tid >> 5;
    const int i0   = blockIdx.x * IT;
    const int jb   = blockIdx.y;

    if (tid == 0) {
        asm volatile("mbarrier.init.shared::cta.b64 [%0], %1;" :: "r"(mbar), "r"(1) : "memory");
    }
    __syncthreads();
    if (tid == 0) {
        asm volatile("mbarrier.arrive.expect_tx.shared::cta.b64 _, [%0], %1;"
                     :: "r"(mbar), "r"(51200) : "memory");
        asm volatile("cp.async.bulk.shared::cta.global.mbarrier::complete_tx::bytes [%0], [%1], %2, [%3];"
                     :: "r"(sb + SM_GS), "l"(g_dgT + (size_t)jb * 10240), "r"(40960), "r"(mbar) : "memory");
        asm volatile("cp.async.bulk.shared::cta.global.mbarrier::complete_tx::bytes [%0], [%1], %2, [%3];"
                     :: "r"(sb + SM_CS), "l"(g_ctilde + (size_t)i0 * 160), "r"(10240), "r"(mbar) : "memory");
    }
    asm volatile("{\n\t.reg .pred P;\n"
                 "W%=: mbarrier.try_wait.parity.shared::cta.b64 P, [%0], 0;\n\t"
                 "@!P bra W%=;\n\t}" :: "r"(mbar) : "memory");
    __syncthreads();

    const int jj = tid & 63;
    const int ig = tid >> 6;

    ull acc[TI][10];
#pragma unroll
    for (int r = 0; r < TI; r++)
#pragma unroll
        for (int q = 0; q < 10; q++) acc[r][q] = 0ULL;

#pragma unroll
    for (int xp = 0; xp < 10; xp++) {
        ulonglong2 g0  = gs2[(xp * 4 + 0) * 64 + jj];
        ulonglong2 g1  = gs2[(xp * 4 + 1) * 64 + jj];
        ulonglong2 g2v = gs2[(xp * 4 + 2) * 64 + jj];
        ulonglong2 g3  = gs2[(xp * 4 + 3) * 64 + jj];
#pragma unroll
        for (int r = 0; r < TI; r++) {
            const float* cp = cs + (ig * 4 + r) * 160 + xp * 16;
            longlong2 ca = *(const longlong2*)(cp);
            longlong2 cb = *(const longlong2*)(cp + 4);
            longlong2 cc = *(const longlong2*)(cp + 8);
            longlong2 cd = *(const longlong2*)(cp + 12);
            ull a0 = acc[r][xp];
            a0 = fma2((ull)ca.x, g0.x, a0);
            a0 = fma2((ull)ca.y, g0.y, a0);
            a0 = fma2((ull)cb.x, g1.x, a0);
            a0 = fma2((ull)cb.y, g1.y, a0);
            a0 = fma2((ull)cc.x, g2v.x, a0);
            a0 = fma2((ull)cc.y, g2v.y, a0);
            a0 = fma2((ull)cd.x, g3.x, a0);
            a0 = fma2((ull)cd.y, g3.y, a0);
            acc[r][xp] = a0;
        }
    }

    // ---- epilogue: log_softmax, stage (conflict-free STS.128), bulk store ----
    float* wbuf = (float*)(sm + SM_STG) + wid * 1280;
    const uint32_t wbuf_u32 = sb + SM_STG + wid * 5120;
    const int col0 = jb * JT + (wid & 1) * 32;

#pragma unroll
    for (int r = 0; r < TI; r++) {
        float* st = wbuf + (r & 1) * 640;
        if (r >= 2 && lane == 0)
            asm volatile("cp.async.bulk.wait_group.read 1;" ::: "memory");
        __syncwarp();

        float l[20];
#pragma unroll
        for (int q = 0; q < 10; q++) {
            l[2 * q]     = __uint_as_float((unsigned)(acc[r][q] & 0xffffffffu));
            l[2 * q + 1] = __uint_as_float((unsigned)(acc[r][q] >> 32));
        }
        float m = l[0];
#pragma unroll
        for (int x = 1; x < 20; x++) m = fmaxf(m, l[x]);
        float s = 0.f;
#pragma unroll
        for (int x = 0; x < 20; x++) s += __expf(l[x] - m);
        float lse = m + __logf(s);

        float* tp = st + lane * 20;
#pragma unroll
        for (int q = 0; q < 5; q++) {
            float4 o = make_float4(l[4 * q] - lse, l[4 * q + 1] - lse,
                                   l[4 * q + 2] - lse, l[4 * q + 3] - lse);
            *(float4*)(tp + 4 * q) = o;
        }
        __syncwarp();

        if (lane == 0) {
            float* gdst = out + ((size_t)(i0 + ig * 4 + r) * NN + col0) * NAA;
            asm volatile("fence.proxy.async.shared::cta;" ::: "memory");
            asm volatile("cp.async.bulk.global.shared::cta.bulk_group [%0], [%1], %2;"
                         :: "l"(gdst), "r"(wbuf_u32 + (r & 1) * 2560), "r"(2560) : "memory");
            asm volatile("cp.async.bulk.commit_group;" ::: "memory");
        }
    }
    if (lane == 0)
        asm volatile("cp.async.bulk.wait_group 0;" ::: "memory");
}

// ============================================================================
extern "C" void kernel_launch(void* const* d_in, const int* in_sizes, int n_in,
                              void* d_out, int out_size)
{
    const float* local = (const float*)d_in[0];
    const int*   aa    = (const int*)d_in[1];
    const float* W1    = (const float*)d_in[2];
    const float* W2    = (const float*)d_in[3];
    const float* Wc    = (const float*)d_in[4];
    const float* Wg    = (const float*)d_in[5];
    const float* iw    = (const float*)d_in[6];
    float* out = (float*)d_out;

    prep_kernel<<<NN / TM, 256>>>(local, aa, W1, W2, Wc, Wg, iw);

    cudaFuncSetAttribute(pair_kernel, cudaFuncAttributeMaxDynamicSharedMemorySize, SM_TOT);

    cudaLaunchConfig_t cfg = {};
    cfg.gridDim = dim3(NN / IT, NN / JT);
    cfg.blockDim = dim3(256, 1, 1);
    cfg.dynamicSmemBytes = SM_TOT;
    cfg.stream = 0;
    cudaLaunchAttribute attrs[1];
    attrs[0].id = cudaLaunchAttributeProgrammaticStreamSerialization;
    attrs[0].val.programmaticStreamSerializationAllowed = 1;
    cfg.attrs = attrs;
    cfg.numAttrs = 1;
    cudaLaunchKernelEx(&cfg, pair_kernel, out);
}